// round 10
// baseline (speedup 1.0000x reference)
#include <cuda_runtime.h>
#include <cstdint>

#define NNODE 20000
#define DDEG  16

typedef unsigned long long ull;

// ---------------- scratch (device globals; no allocations) ----------------
__device__ float g_WTih1[128 * 512];
__device__ float g_WThh1[128 * 512];
__device__ float g_WTih2[128 * 512];
__device__ float g_WThh2[128 * 512];
__device__ float g_WTself[128 * 128];
__device__ float g_WTneigh[128 * 128];
__device__ float g_Xp[(size_t)NNODE * 512];   // input projection (+bias)
__device__ float g_H[(size_t)NNODE * 128];    // LSTM final hidden
__device__ float g_h1[(size_t)NNODE * 128];   // layer-1 output

// ---------------- helpers ----------------
__device__ __forceinline__ float tanh_f(float x) {
    float y;
    asm("tanh.approx.f32 %0, %1;" : "=f"(y) : "f"(x));
    return y;
}
// sigmoid(x) = 0.5*tanh(x/2) + 0.5  (1 MUFU + 2 FMA)
__device__ __forceinline__ float sig_f(float x) {
    return fmaf(0.5f, tanh_f(0.5f * x), 0.5f);
}
__device__ __forceinline__ float sig_exact(float x) { return 1.f / (1.f + __expf(-x)); }

// Packed fp32x2 FMA (Blackwell FFMA2)
__device__ __forceinline__ ull fma2(ull a, ull b, ull c) {
    ull d;
    asm("fma.rn.f32x2 %0, %1, %2, %3;" : "=l"(d) : "l"(a), "l"(b), "l"(c));
    return d;
}
__device__ __forceinline__ ull pack2(float x, float y) {
    ull d;
    asm("mov.b64 %0, {%1, %2};" : "=l"(d) : "f"(x), "f"(y));
    return d;
}
__device__ __forceinline__ float2 unpack2(ull v) {
    float2 r;
    asm("mov.b64 {%0, %1}, %2;" : "=f"(r.x), "=f"(r.y) : "l"(v));
    return r;
}

__device__ __forceinline__ unsigned smem_u32(const void* p) {
    return (unsigned)__cvta_generic_to_shared(p);
}
__device__ __forceinline__ void cp_async16(unsigned saddr, const void* g) {
    asm volatile("cp.async.ca.shared.global [%0], [%1], 16;\n" :: "r"(saddr), "l"(g) : "memory");
}
__device__ __forceinline__ void cp_commit() { asm volatile("cp.async.commit_group;\n" ::: "memory"); }
__device__ __forceinline__ void cp_wait0()  { asm volatile("cp.async.wait_group 0;\n" ::: "memory"); }

// ---------------- batched transpose: all 6 weight matrices, 1 launch ------
// Segments: 4x [512x128] then 2x [128x128]. WT[k*R+r] = W[r*K+k], K=128.
__global__ void transpose_all_kernel(
    const float* __restrict__ Wih1, const float* __restrict__ Whh1,
    const float* __restrict__ Wih2, const float* __restrict__ Whh2,
    const float* __restrict__ Wself, const float* __restrict__ Wneigh,
    float* __restrict__ WTih1, float* __restrict__ WThh1,
    float* __restrict__ WTih2, float* __restrict__ WThh2,
    float* __restrict__ WTself, float* __restrict__ WTneigh)
{
    int i = blockIdx.x * blockDim.x + threadIdx.x;
    const float* src;
    float* dst;
    int R, local;
    if (i < 262144) {                       // four 512x128 matrices
        int seg = i >> 16;                  // 65536 each
        local = i & 65535;
        R = 512;
        src = (seg == 0) ? Wih1 : (seg == 1) ? Whh1 : (seg == 2) ? Wih2 : Whh2;
        dst = (seg == 0) ? WTih1 : (seg == 1) ? WThh1 : (seg == 2) ? WTih2 : WThh2;
    } else if (i < 294912) {                // two 128x128 matrices
        int j = i - 262144;
        int seg = j >> 14;                  // 16384 each
        local = j & 16383;
        R = 128;
        src = (seg == 0) ? Wself : Wneigh;
        dst = (seg == 0) ? WTself : WTneigh;
    } else return;
    int r = local >> 7, k = local & 127;
    dst[k * R + r] = src[local];
}

// ---------------- generic fused GEMM (f32x2 inner loop) ----------------
// C[N,M] = act( A@WT + (A2?A2@WT2:0) + b1 + (b2?b2:0) ),  K=128
#define GEMM_SMEM ((64 * 132 + 128 * 68) * 4)
__global__ __launch_bounds__(256) void fused_gemm_kernel(
    const float* __restrict__ A,  const float* __restrict__ WT,
    const float* __restrict__ A2, const float* __restrict__ WT2,
    const float* __restrict__ b1, const float* __restrict__ b2,
    float* __restrict__ C, int Nrows, int M, int act)
{
    extern __shared__ float sm[];
    float* As = sm;               // [64][132] row-major
    float* Ws = sm + 64 * 132;    // [128][68] k-major
    int tid = threadIdx.x;
    int tx = tid & 15, ty = tid >> 4;
    int rowBase = blockIdx.y * 64, colBase = blockIdx.x * 64;

    ull acc[4][2];
#pragma unroll
    for (int i = 0; i < 4; i++) { acc[i][0] = 0ull; acc[i][1] = 0ull; }

    int npass = (A2 != nullptr) ? 2 : 1;
    for (int pass = 0; pass < npass; ++pass) {
        const float* Ap = pass ? A2 : A;
        const float* Wp = pass ? WT2 : WT;
        if (pass) __syncthreads();
        for (int f = tid; f < 64 * 32; f += 256) {
            int r = f >> 5, c4 = f & 31;
            float4 v = make_float4(0.f, 0.f, 0.f, 0.f);
            if (rowBase + r < Nrows)
                v = *(const float4*)(Ap + (size_t)(rowBase + r) * 128 + c4 * 4);
            *(float4*)(As + r * 132 + c4 * 4) = v;
        }
        for (int f = tid; f < 128 * 16; f += 256) {
            int k = f >> 4, c4 = f & 15;
            *(float4*)(Ws + k * 68 + c4 * 4) =
                *(const float4*)(Wp + (size_t)k * M + colBase + c4 * 4);
        }
        __syncthreads();
#pragma unroll 8
        for (int k = 0; k < 128; k++) {
            ulonglong2 w = *(const ulonglong2*)(Ws + k * 68 + tx * 4);
#pragma unroll
            for (int i = 0; i < 4; i++) {
                float a = As[(ty * 4 + i) * 132 + k];
                ull aa = pack2(a, a);
                acc[i][0] = fma2(aa, w.x, acc[i][0]);
                acc[i][1] = fma2(aa, w.y, acc[i][1]);
            }
        }
    }
#pragma unroll
    for (int i = 0; i < 4; i++) {
        int row = rowBase + ty * 4 + i;
        if (row < Nrows) {
            float2 v01 = unpack2(acc[i][0]);
            float2 v23 = unpack2(acc[i][1]);
            float vv[4] = {v01.x, v01.y, v23.x, v23.y};
#pragma unroll
            for (int j = 0; j < 4; j++) {
                int col = colBase + tx * 4 + j;
                float v = vv[j] + b1[col];
                if (b2) v += b2[col];
                if (act) v = fmaxf(v, 0.f);
                C[(size_t)row * M + col] = v;
            }
        }
    }
}

// ---------------- persistent LSTM layer ----------------
// Block: 32 nodes, 256 threads. Thread = 8 nodes x 2 units.
// Continuous cross-step W-tile pipeline (no per-step prologue stall),
// gathers for t+1 hoisted before the next pipeline barrier.
#define LSTM_SMEM (128 * 36 * 4 + 2 * 16 * 520 * 4 + 32 * DDEG * 4)
__global__ __launch_bounds__(256, 2) void lstm_kernel(
    const float* __restrict__ Xp, const int* __restrict__ nbr,
    const float* __restrict__ WThh, float* __restrict__ Hout)
{
    extern __shared__ float sm[];
    float* Hs  = sm;                        // [128 units][36] (32 nodes + pad)
    float* Wsb = sm + 128 * 36;             // [2][16][520] double-buffered k-tiles
    int* idx_s = (int*)(sm + 128 * 36 + 2 * 16 * 520);

    int tid = threadIdx.x;
    int ug = tid & 63, ng = tid >> 6;
    int u0 = ug * 2, nloc0 = ng * 8;
    int nodeBase = blockIdx.x * 32;

    for (int i = tid; i < 32 * DDEG; i += 256)
        idx_s[i] = nbr[(size_t)(nodeBase + (i >> 4)) * DDEG + (i & 15)];
    __syncthreads();

    float c0[8], c1[8];
#pragma unroll
    for (int i = 0; i < 8; i++) { c0[i] = 0.f; c1[i] = 0.f; }

#define ISSUE_TILE(ktile, dst)                                            \
    {                                                                     \
        float* _d = (dst);                                                \
        _Pragma("unroll")                                                 \
        for (int q = 0; q < 8; q++) {                                     \
            int f = q * 256 + tid;                                        \
            int k = f >> 7, c4 = f & 127;                                 \
            cp_async16(smem_u32(_d + k * 520 + c4 * 4),                   \
                       WThh + ((size_t)((ktile) * 16 + k) * 512 + c4 * 4)); \
        }                                                                 \
        cp_commit();                                                      \
    }

    // --- gather for t=0 ---
    ull aI[8], aF[8], aG[8], aO[8];
#pragma unroll
    for (int i = 0; i < 8; i++) {
        int row = idx_s[(nloc0 + i) * DDEG + 0];
        const float* xr = Xp + (size_t)row * 512 + u0;
        aI[i] = *(const ull*)(xr);
        aF[i] = *(const ull*)(xr + 128);
        aG[i] = *(const ull*)(xr + 256);
        aO[i] = *(const ull*)(xr + 384);
    }
    // --- global pipeline prologue: W tile 0 -> buf 0 (for t=1) ---
    ISSUE_TILE(0, Wsb);

    for (int t = 0; t < DDEG; ++t) {
        // --- recurrent GEMM (t=0 skipped: h=0) ---
        if (t > 0) {
            for (int kt = 0; kt < 8; ++kt) {
                // tile kt was issued one compute-block (or epilogue) ago
                cp_wait0();
                // barrier: (a) everyone's slice of tile kt visible,
                //          (b) buffer (kt+1)&1 free (tile kt-1 computed by all),
                //          (c) for kt==0: previous step's Hs stores visible
                __syncthreads();
                if (!(t == DDEG - 1 && kt == 7)) {
                    // next tile in the stream; kt==7 wraps to tile 0 of step t+1
                    ISSUE_TILE((kt + 1) & 7, Wsb + ((kt + 1) & 1) * 16 * 520);
                }
                const float* W = Wsb + (kt & 1) * 16 * 520;
#pragma unroll 4
                for (int k = 0; k < 16; k++) {
                    int kk = kt * 16 + k;
                    float4 hA = *(const float4*)(Hs + kk * 36 + nloc0);
                    float4 hB = *(const float4*)(Hs + kk * 36 + nloc0 + 4);
                    ull wi = *(const ull*)(W + k * 520 + u0);
                    ull wf = *(const ull*)(W + k * 520 + 128 + u0);
                    ull wg = *(const ull*)(W + k * 520 + 256 + u0);
                    ull wo = *(const ull*)(W + k * 520 + 384 + u0);
#define STEPN(i, hv)                                   \
    {                                                  \
        ull hh = pack2((hv), (hv));                    \
        aI[i] = fma2(hh, wi, aI[i]);                   \
        aF[i] = fma2(hh, wf, aF[i]);                   \
        aG[i] = fma2(hh, wg, aG[i]);                   \
        aO[i] = fma2(hh, wo, aO[i]);                   \
    }
                    STEPN(0, hA.x) STEPN(1, hA.y) STEPN(2, hA.z) STEPN(3, hA.w)
                    STEPN(4, hB.x) STEPN(5, hB.y) STEPN(6, hB.z) STEPN(7, hB.w)
#undef STEPN
                }
            }
            // all warps finished reading Hs (tile 7) before epilogue overwrites
            __syncthreads();
        }
        // --- cell update (PyTorch gate order i,f,g,o), MUFU approx math ---
        float hv0[8], hv1[8];
#pragma unroll
        for (int i = 0; i < 8; i++) {
            float2 vi = unpack2(aI[i]);
            float2 vf = unpack2(aF[i]);
            float2 vg = unpack2(aG[i]);
            float2 vo = unpack2(aO[i]);
            c0[i]  = sig_f(vf.x) * c0[i] + sig_f(vi.x) * tanh_f(vg.x);
            hv0[i] = sig_f(vo.x) * tanh_f(c0[i]);
            c1[i]  = sig_f(vf.y) * c1[i] + sig_f(vi.y) * tanh_f(vg.y);
            hv1[i] = sig_f(vo.y) * tanh_f(c1[i]);
        }
        if (t < DDEG - 1) {
            // store h for next step's GEMM (ordered by next step's first barrier)
            *(float4*)(Hs + u0 * 36 + nloc0)           = make_float4(hv0[0], hv0[1], hv0[2], hv0[3]);
            *(float4*)(Hs + u0 * 36 + nloc0 + 4)       = make_float4(hv0[4], hv0[5], hv0[6], hv0[7]);
            *(float4*)(Hs + (u0 + 1) * 36 + nloc0)     = make_float4(hv1[0], hv1[1], hv1[2], hv1[3]);
            *(float4*)(Hs + (u0 + 1) * 36 + nloc0 + 4) = make_float4(hv1[4], hv1[5], hv1[6], hv1[7]);
            // gather for t+1 now (accs are dead) — LDG latency hides under
            // the next barrier + tile wait + issue
#pragma unroll
            for (int i = 0; i < 8; i++) {
                int row = idx_s[(nloc0 + i) * DDEG + (t + 1)];
                const float* xr = Xp + (size_t)row * 512 + u0;
                aI[i] = *(const ull*)(xr);
                aF[i] = *(const ull*)(xr + 128);
                aG[i] = *(const ull*)(xr + 256);
                aO[i] = *(const ull*)(xr + 384);
            }
        } else {
#pragma unroll
            for (int i = 0; i < 8; i++) {
                int n = nodeBase + nloc0 + i;
                *(float2*)(Hout + (size_t)n * 128 + u0) = make_float2(hv0[i], hv1[i]);
            }
        }
    }
#undef ISSUE_TILE
}

// ---------------- final layer-2 combine: OUT=1 + sigmoid ----------------
__global__ void out_kernel(const float* __restrict__ h1, const float* __restrict__ H,
                           const float* __restrict__ Wself, const float* __restrict__ Wneigh,
                           const float* __restrict__ b, float* __restrict__ out, int Nrows)
{
    int gwarp = (blockIdx.x * blockDim.x + threadIdx.x) >> 5;
    int lane = threadIdx.x & 31;
    if (gwarp >= Nrows) return;
    float s = 0.f;
#pragma unroll
    for (int q = 0; q < 4; q++) {
        int k = lane + 32 * q;
        s += h1[(size_t)gwarp * 128 + k] * Wself[k] + H[(size_t)gwarp * 128 + k] * Wneigh[k];
    }
#pragma unroll
    for (int off = 16; off; off >>= 1) s += __shfl_xor_sync(0xFFFFFFFFu, s, off);
    if (lane == 0) out[gwarp] = sig_exact(s + b[0]);
}

// ---------------- launch ----------------
extern "C" void kernel_launch(void* const* d_in, const int* in_sizes, int n_in,
                              void* d_out, int out_size)
{
    const float* x       = (const float*)d_in[0];
    const int*   nbr     = (const int*)d_in[1];
    const float* Wih1    = (const float*)d_in[2];
    const float* Whh1    = (const float*)d_in[3];
    const float* bih1    = (const float*)d_in[4];
    const float* bhh1    = (const float*)d_in[5];
    const float* Wself1  = (const float*)d_in[6];
    const float* Wneigh1 = (const float*)d_in[7];
    const float* bneigh1 = (const float*)d_in[8];
    const float* Wih2    = (const float*)d_in[9];
    const float* Whh2    = (const float*)d_in[10];
    const float* bih2    = (const float*)d_in[11];
    const float* bhh2    = (const float*)d_in[12];
    const float* Wself2  = (const float*)d_in[13];
    const float* Wneigh2 = (const float*)d_in[14];
    const float* bneigh2 = (const float*)d_in[15];
    float* out = (float*)d_out;

    float *WTih1, *WThh1, *WTih2, *WThh2, *WTself, *WTneigh, *Xp, *H, *h1;
    cudaGetSymbolAddress((void**)&WTih1,   g_WTih1);
    cudaGetSymbolAddress((void**)&WThh1,   g_WThh1);
    cudaGetSymbolAddress((void**)&WTih2,   g_WTih2);
    cudaGetSymbolAddress((void**)&WThh2,   g_WThh2);
    cudaGetSymbolAddress((void**)&WTself,  g_WTself);
    cudaGetSymbolAddress((void**)&WTneigh, g_WTneigh);
    cudaGetSymbolAddress((void**)&Xp,      g_Xp);
    cudaGetSymbolAddress((void**)&H,       g_H);
    cudaGetSymbolAddress((void**)&h1,      g_h1);

    cudaFuncSetAttribute(fused_gemm_kernel, cudaFuncAttributeMaxDynamicSharedMemorySize, GEMM_SMEM);
    cudaFuncSetAttribute(lstm_kernel,       cudaFuncAttributeMaxDynamicSharedMemorySize, LSTM_SMEM);

    const int TB = 256;
    // 1) all transposes, one launch
    transpose_all_kernel<<<(294912 + TB - 1) / TB, TB>>>(
        Wih1, Whh1, Wih2, Whh2, Wself1, Wneigh1,
        WTih1, WThh1, WTih2, WThh2, WTself, WTneigh);

    // ---- layer 1 ----
    fused_gemm_kernel<<<dim3(8, 313), TB, GEMM_SMEM>>>(
        x, WTih1, nullptr, nullptr, bih1, bhh1, Xp, NNODE, 512, 0);
    lstm_kernel<<<NNODE / 32, TB, LSTM_SMEM>>>(Xp, nbr, WThh1, H);
    fused_gemm_kernel<<<dim3(2, 313), TB, GEMM_SMEM>>>(
        x, WTself, H, WTneigh, bneigh1, nullptr, h1, NNODE, 128, 1);

    // ---- layer 2 ----
    fused_gemm_kernel<<<dim3(8, 313), TB, GEMM_SMEM>>>(
        h1, WTih2, nullptr, nullptr, bih2, bhh2, Xp, NNODE, 512, 0);
    lstm_kernel<<<NNODE / 32, TB, LSTM_SMEM>>>(Xp, nbr, WThh2, H);
    out_kernel<<<(NNODE * 32 + TB - 1) / TB, TB>>>(h1, H, Wself2, Wneigh2, bneigh2, out, NNODE);
}

// round 12
// speedup vs baseline: 2.4363x; 2.4363x over previous
#include <cuda_runtime.h>
#include <cuda_bf16.h>
#include <cstdint>

#define NNODE 20000
#define DDEG  16

typedef unsigned long long ull;

// ---------------- scratch (device globals; no allocations) ----------------
__device__ float g_WTih1[128 * 512];
__device__ float g_WTih2[128 * 512];
__device__ float g_WTself[128 * 128];
__device__ float g_WTneigh[128 * 128];
__device__ float g_Xp[(size_t)NNODE * 512];   // input projection (+bias)
__device__ float g_H[(size_t)NNODE * 128];    // LSTM final hidden
__device__ float g_h1[(size_t)NNODE * 128];   // layer-1 output

// ---------------- math helpers ----------------
__device__ __forceinline__ float tanh_f(float x) {
    float y; asm("tanh.approx.f32 %0, %1;" : "=f"(y) : "f"(x)); return y;
}
__device__ __forceinline__ float sig_f(float x) {
    return fmaf(0.5f, tanh_f(0.5f * x), 0.5f);
}
__device__ __forceinline__ float sig_exact(float x) { return 1.f / (1.f + __expf(-x)); }

__device__ __forceinline__ ull fma2(ull a, ull b, ull c) {
    ull d; asm("fma.rn.f32x2 %0, %1, %2, %3;" : "=l"(d) : "l"(a), "l"(b), "l"(c)); return d;
}
__device__ __forceinline__ ull pack2(float x, float y) {
    ull d; asm("mov.b64 %0, {%1, %2};" : "=l"(d) : "f"(x), "f"(y)); return d;
}
__device__ __forceinline__ float2 unpack2(ull v) {
    float2 r; asm("mov.b64 {%0, %1}, %2;" : "=f"(r.x), "=f"(r.y) : "l"(v)); return r;
}
// pack two fp32 -> bf16x2 (lo in low half)
__device__ __forceinline__ uint32_t bf16x2_pack(float hi, float lo) {
    uint32_t r; asm("cvt.rn.bf16x2.f32 %0, %1, %2;" : "=r"(r) : "f"(hi), "f"(lo)); return r;
}

// Ampere-class bf16 tensor-core MMA (plain PTX, no sm_103a-only features).
// D(16x8,f32) += A(16x16,bf16) * B(16x8,bf16)
__device__ __forceinline__ void mma_bf16(float* d, const uint32_t* a, uint32_t b0, uint32_t b1) {
    asm volatile(
        "mma.sync.aligned.m16n8k16.row.col.f32.bf16.bf16.f32 "
        "{%0,%1,%2,%3}, {%4,%5,%6,%7}, {%8,%9}, {%0,%1,%2,%3};"
        : "+f"(d[0]), "+f"(d[1]), "+f"(d[2]), "+f"(d[3])
        : "r"(a[0]), "r"(a[1]), "r"(a[2]), "r"(a[3]), "r"(b0), "r"(b1));
}

// ---------------- batched transpose: Wih1, Wih2, Wself, Wneigh ------------
__global__ void transpose_all_kernel(
    const float* __restrict__ Wih1, const float* __restrict__ Wih2,
    const float* __restrict__ Wself, const float* __restrict__ Wneigh,
    float* __restrict__ WTih1, float* __restrict__ WTih2,
    float* __restrict__ WTself, float* __restrict__ WTneigh)
{
    int i = blockIdx.x * blockDim.x + threadIdx.x;
    const float* src; float* dst; int R, local;
    if (i < 131072) {                 // two 512x128
        int seg = i >> 16; local = i & 65535; R = 512;
        src = seg ? Wih2 : Wih1; dst = seg ? WTih2 : WTih1;
    } else if (i < 163840) {          // two 128x128
        int j = i - 131072; int seg = j >> 14; local = j & 16383; R = 128;
        src = seg ? Wneigh : Wself; dst = seg ? WTneigh : WTself;
    } else return;
    int r = local >> 7, k = local & 127;
    dst[k * R + r] = src[local];
}

// ---------------- generic fused GEMM (f32x2 inner loop) ----------------
#define GEMM_SMEM ((64 * 132 + 128 * 68) * 4)
__global__ __launch_bounds__(256) void fused_gemm_kernel(
    const float* __restrict__ A,  const float* __restrict__ WT,
    const float* __restrict__ A2, const float* __restrict__ WT2,
    const float* __restrict__ b1, const float* __restrict__ b2,
    float* __restrict__ C, int Nrows, int M, int act)
{
    extern __shared__ float sm[];
    float* As = sm;
    float* Ws = sm + 64 * 132;
    int tid = threadIdx.x;
    int tx = tid & 15, ty = tid >> 4;
    int rowBase = blockIdx.y * 64, colBase = blockIdx.x * 64;

    ull acc[4][2];
#pragma unroll
    for (int i = 0; i < 4; i++) { acc[i][0] = 0ull; acc[i][1] = 0ull; }

    int npass = (A2 != nullptr) ? 2 : 1;
    for (int pass = 0; pass < npass; ++pass) {
        const float* Ap = pass ? A2 : A;
        const float* Wp = pass ? WT2 : WT;
        if (pass) __syncthreads();
        for (int f = tid; f < 64 * 32; f += 256) {
            int r = f >> 5, c4 = f & 31;
            float4 v = make_float4(0.f, 0.f, 0.f, 0.f);
            if (rowBase + r < Nrows)
                v = *(const float4*)(Ap + (size_t)(rowBase + r) * 128 + c4 * 4);
            *(float4*)(As + r * 132 + c4 * 4) = v;
        }
        for (int f = tid; f < 128 * 16; f += 256) {
            int k = f >> 4, c4 = f & 15;
            *(float4*)(Ws + k * 68 + c4 * 4) =
                *(const float4*)(Wp + (size_t)k * M + colBase + c4 * 4);
        }
        __syncthreads();
#pragma unroll 8
        for (int k = 0; k < 128; k++) {
            ulonglong2 w = *(const ulonglong2*)(Ws + k * 68 + tx * 4);
#pragma unroll
            for (int i = 0; i < 4; i++) {
                float a = As[(ty * 4 + i) * 132 + k];
                ull aa = pack2(a, a);
                acc[i][0] = fma2(aa, w.x, acc[i][0]);
                acc[i][1] = fma2(aa, w.y, acc[i][1]);
            }
        }
    }
#pragma unroll
    for (int i = 0; i < 4; i++) {
        int row = rowBase + ty * 4 + i;
        if (row < Nrows) {
            float2 v01 = unpack2(acc[i][0]);
            float2 v23 = unpack2(acc[i][1]);
            float vv[4] = {v01.x, v01.y, v23.x, v23.y};
#pragma unroll
            for (int j = 0; j < 4; j++) {
                int col = colBase + tx * 4 + j;
                float v = vv[j] + b1[col];
                if (b2) v += b2[col];
                if (act) v = fmaxf(v, 0.f);
                C[(size_t)row * M + col] = v;
            }
        }
    }
}

// ---------------- HMMA LSTM layer ----------------
// Block = 128 nodes, 8 warps. Warp w owns node rows [16w,16w+16), all 512 gate
// cols. Recurrent GEMM D[16,512] = h[16,128]bf16 @ Whh^T via m16n8k16 mma.
// A (h) lives in a fragment-ready double-buffered SMEM region written by the
// SAME lane that reads it (D-fragment layout == A-fragment layout) -> the
// 16-step main loop needs NO block/warp synchronization at all.
// SMEM: B_frag 128KB | A_frag 2x32KB | idx 8KB = 200KB.
#define LSTM_SMEM (131072 + 65536 + 8192)
__global__ void __launch_bounds__(256, 1) lstm_mma_kernel(
    const float* __restrict__ Xp, const int* __restrict__ nbr,
    const float* __restrict__ Whh, float* __restrict__ Hout)
{
    extern __shared__ char smem[];
    ull*      Bf    = (ull*)smem;                          // [ks8][nt64][lane32] 2-reg frags
    uint32_t* Af    = (uint32_t*)(smem + 131072);          // [buf2][w8][ks8][lane32][slot4]
    int*      idx_s = (int*)(smem + 131072 + 65536);       // [128][16]

    int tid = threadIdx.x;
    int lane = tid & 31, w = tid >> 5;
    int gr = lane >> 2, tq = lane & 3;
    int nodeBase = blockIdx.x * 128;

    // ---- build fragment-ready B = Whh(n=gate_row, k=unit), bf16 ----
    for (int i = tid; i < 16384; i += 256) {     // i = ks*2048 + nt*32 + lane
        int l = i & 31, nt = (i >> 5) & 63, ks = i >> 11;
        int n = nt * 8 + (l >> 2);
        int k0 = ks * 16 + 2 * (l & 3);
        const float* wr = Whh + (size_t)n * 128;
        float2 p0 = *(const float2*)(wr + k0);
        float2 p1 = *(const float2*)(wr + k0 + 8);
        uint32_t r0 = bf16x2_pack(p0.y, p0.x);
        uint32_t r1 = bf16x2_pack(p1.y, p1.x);
        Bf[i] = ((ull)r1 << 32) | r0;
    }
    // ---- neighbor indices for the whole block ----
    for (int i = tid; i < 128 * 16; i += 256) {
        int node = nodeBase + (i >> 4);
        idx_s[i] = (node < NNODE) ? nbr[(size_t)node * DDEG + (i & 15)] : 0;
    }
    __syncthreads();

    int node0 = nodeBase + w * 16 + gr;      // row r owner
    int node1 = node0 + 8;                   // row r+8 owner
    float c[4][4][4];                        // [uc][j][p]
#pragma unroll
    for (int a = 0; a < 4; a++)
#pragma unroll
        for (int b = 0; b < 4; b++)
#pragma unroll
            for (int p = 0; p < 4; p++) c[a][b][p] = 0.f;

#pragma unroll 1
    for (int t = 0; t < DDEG; ++t) {
        const float* x0 = Xp + (size_t)idx_s[(w * 16 + gr) * DDEG + t] * 512;
        const float* x1 = Xp + (size_t)idx_s[(w * 16 + gr + 8) * DDEG + t] * 512;
        // A buffers: read what step t-1 wrote; write for step t+1
        uint32_t* Ard = Af + ((t & 1) ^ 1) * 8192 + w * 1024;
        uint32_t* Awr = Af + (t & 1) * 8192 + w * 1024;

#pragma unroll
        for (int uc = 0; uc < 4; ++uc) {
            float d[4][4][4];                // [gate][j][p]
#pragma unroll
            for (int g = 0; g < 4; g++)
#pragma unroll
                for (int j = 0; j < 4; j++)
#pragma unroll
                    for (int p = 0; p < 4; p++) d[g][j][p] = 0.f;

            if (t > 0) {
#pragma unroll
                for (int ks = 0; ks < 8; ++ks) {
                    uint4 av = *(uint4*)(Ard + ks * 128 + lane * 4);
                    uint32_t a[4] = {av.x, av.y, av.z, av.w};
#pragma unroll
                    for (int g = 0; g < 4; ++g) {
#pragma unroll
                        for (int j = 0; j < 4; ++j) {
                            int nt = g * 16 + uc * 4 + j;
                            ull bb = Bf[ks * 2048 + nt * 32 + lane];
                            mma_bf16(d[g][j], a, (uint32_t)bb, (uint32_t)(bb >> 32));
                        }
                    }
                }
            }
            // ---- epilogue: gates + cell update for 32 units (this uc) ----
#pragma unroll
            for (int j = 0; j < 4; ++j) {
                int u0 = uc * 32 + j * 8 + 2 * tq;
                float2 xi0 = *(const float2*)(x0 + u0);
                float2 xf0 = *(const float2*)(x0 + 128 + u0);
                float2 xg0 = *(const float2*)(x0 + 256 + u0);
                float2 xo0 = *(const float2*)(x0 + 384 + u0);
                float2 xi1 = *(const float2*)(x1 + u0);
                float2 xf1 = *(const float2*)(x1 + 128 + u0);
                float2 xg1 = *(const float2*)(x1 + 256 + u0);
                float2 xo1 = *(const float2*)(x1 + 384 + u0);

                float gi[4] = {d[0][j][0] + xi0.x, d[0][j][1] + xi0.y,
                               d[0][j][2] + xi1.x, d[0][j][3] + xi1.y};
                float gf[4] = {d[1][j][0] + xf0.x, d[1][j][1] + xf0.y,
                               d[1][j][2] + xf1.x, d[1][j][3] + xf1.y};
                float gg[4] = {d[2][j][0] + xg0.x, d[2][j][1] + xg0.y,
                               d[2][j][2] + xg1.x, d[2][j][3] + xg1.y};
                float go[4] = {d[3][j][0] + xo0.x, d[3][j][1] + xo0.y,
                               d[3][j][2] + xo1.x, d[3][j][3] + xo1.y};
                float h_[4];
#pragma unroll
                for (int p = 0; p < 4; ++p) {
                    float cn = sig_f(gf[p]) * c[uc][j][p] + sig_f(gi[p]) * tanh_f(gg[p]);
                    c[uc][j][p] = cn;
                    h_[p] = sig_f(go[p]) * tanh_f(cn);
                }
                if (t < DDEG - 1) {
                    // write fragment-ready A for next step (same-lane read)
                    uint32_t lo = bf16x2_pack(h_[1], h_[0]);   // row r
                    uint32_t hi = bf16x2_pack(h_[3], h_[2]);   // row r+8
                    int ks = uc * 2 + (j >> 1);
                    int slot = (j & 1) * 2;
                    *(ull*)(Awr + ks * 128 + lane * 4 + slot) = ((ull)hi << 32) | lo;
                } else {
                    if (node0 < NNODE)
                        *(float2*)(Hout + (size_t)node0 * 128 + u0) = make_float2(h_[0], h_[1]);
                    if (node1 < NNODE)
                        *(float2*)(Hout + (size_t)node1 * 128 + u0) = make_float2(h_[2], h_[3]);
                }
            }
        }
    }
}

// ---------------- final layer-2 combine: OUT=1 + sigmoid ----------------
__global__ void out_kernel(const float* __restrict__ h1, const float* __restrict__ H,
                           const float* __restrict__ Wself, const float* __restrict__ Wneigh,
                           const float* __restrict__ b, float* __restrict__ out, int Nrows)
{
    int gwarp = (blockIdx.x * blockDim.x + threadIdx.x) >> 5;
    int lane = threadIdx.x & 31;
    if (gwarp >= Nrows) return;
    float s = 0.f;
#pragma unroll
    for (int q = 0; q < 4; q++) {
        int k = lane + 32 * q;
        s += h1[(size_t)gwarp * 128 + k] * Wself[k] + H[(size_t)gwarp * 128 + k] * Wneigh[k];
    }
#pragma unroll
    for (int off = 16; off; off >>= 1) s += __shfl_xor_sync(0xFFFFFFFFu, s, off);
    if (lane == 0) out[gwarp] = sig_exact(s + b[0]);
}

// ---------------- launch ----------------
extern "C" void kernel_launch(void* const* d_in, const int* in_sizes, int n_in,
                              void* d_out, int out_size)
{
    const float* x       = (const float*)d_in[0];
    const int*   nbr     = (const int*)d_in[1];
    const float* Wih1    = (const float*)d_in[2];
    const float* Whh1    = (const float*)d_in[3];
    const float* bih1    = (const float*)d_in[4];
    const float* bhh1    = (const float*)d_in[5];
    const float* Wself1  = (const float*)d_in[6];
    const float* Wneigh1 = (const float*)d_in[7];
    const float* bneigh1 = (const float*)d_in[8];
    const float* Wih2    = (const float*)d_in[9];
    const float* Whh2    = (const float*)d_in[10];
    const float* bih2    = (const float*)d_in[11];
    const float* bhh2    = (const float*)d_in[12];
    const float* Wself2  = (const float*)d_in[13];
    const float* Wneigh2 = (const float*)d_in[14];
    const float* bneigh2 = (const float*)d_in[15];
    float* out = (float*)d_out;

    float *WTih1, *WTih2, *WTself, *WTneigh, *Xp, *H, *h1;
    cudaGetSymbolAddress((void**)&WTih1,   g_WTih1);
    cudaGetSymbolAddress((void**)&WTih2,   g_WTih2);
    cudaGetSymbolAddress((void**)&WTself,  g_WTself);
    cudaGetSymbolAddress((void**)&WTneigh, g_WTneigh);
    cudaGetSymbolAddress((void**)&Xp,      g_Xp);
    cudaGetSymbolAddress((void**)&H,       g_H);
    cudaGetSymbolAddress((void**)&h1,      g_h1);

    cudaFuncSetAttribute(fused_gemm_kernel, cudaFuncAttributeMaxDynamicSharedMemorySize, GEMM_SMEM);
    cudaFuncSetAttribute(lstm_mma_kernel,   cudaFuncAttributeMaxDynamicSharedMemorySize, LSTM_SMEM);

    const int TB = 256;
    const int LSTM_GRID = (NNODE + 127) / 128;   // 157

    transpose_all_kernel<<<(163840 + TB - 1) / TB, TB>>>(
        Wih1, Wih2, Wself1, Wneigh1, WTih1, WTih2, WTself, WTneigh);

    // ---- layer 1 ----
    fused_gemm_kernel<<<dim3(8, 313), TB, GEMM_SMEM>>>(
        x, WTih1, nullptr, nullptr, bih1, bhh1, Xp, NNODE, 512, 0);
    lstm_mma_kernel<<<LSTM_GRID, TB, LSTM_SMEM>>>(Xp, nbr, Whh1, H);
    fused_gemm_kernel<<<dim3(2, 313), TB, GEMM_SMEM>>>(
        x, WTself, H, WTneigh, bneigh1, nullptr, h1, NNODE, 128, 1);

    // ---- layer 2 ----
    fused_gemm_kernel<<<dim3(8, 313), TB, GEMM_SMEM>>>(
        h1, WTih2, nullptr, nullptr, bih2, bhh2, Xp, NNODE, 512, 0);
    lstm_mma_kernel<<<LSTM_GRID, TB, LSTM_SMEM>>>(Xp, nbr, Whh2, H);
    out_kernel<<<(NNODE * 32 + TB - 1) / TB, TB>>>(h1, H, Wself2, Wneigh2, bneigh2, out, NNODE);
}

// round 13
// speedup vs baseline: 3.0867x; 1.2670x over previous
#include <cuda_runtime.h>
#include <cuda_bf16.h>
#include <cstdint>

#define NNODE 20000
#define DDEG  16

typedef unsigned long long ull;

// ---------------- scratch (device globals; no allocations) ----------------
__device__ float g_WTih1[128 * 512];
__device__ float g_WTih2[128 * 512];
__device__ float g_WTself[128 * 128];
__device__ float g_WTneigh[128 * 128];
__device__ float g_Xp[(size_t)NNODE * 512];   // input projection (+bias)
__device__ float g_H[(size_t)NNODE * 128];    // LSTM final hidden
__device__ float g_h1[(size_t)NNODE * 128];   // layer-1 output

// ---------------- math helpers ----------------
__device__ __forceinline__ float tanh_f(float x) {
    float y; asm("tanh.approx.f32 %0, %1;" : "=f"(y) : "f"(x)); return y;
}
__device__ __forceinline__ float sig_f(float x) {
    return fmaf(0.5f, tanh_f(0.5f * x), 0.5f);
}
__device__ __forceinline__ float sig_exact(float x) { return 1.f / (1.f + __expf(-x)); }

__device__ __forceinline__ ull fma2(ull a, ull b, ull c) {
    ull d; asm("fma.rn.f32x2 %0, %1, %2, %3;" : "=l"(d) : "l"(a), "l"(b), "l"(c)); return d;
}
__device__ __forceinline__ ull pack2(float x, float y) {
    ull d; asm("mov.b64 %0, {%1, %2};" : "=l"(d) : "f"(x), "f"(y)); return d;
}
__device__ __forceinline__ float2 unpack2(ull v) {
    float2 r; asm("mov.b64 {%0, %1}, %2;" : "=f"(r.x), "=f"(r.y) : "l"(v)); return r;
}
// pack two fp32 -> bf16x2 (lo in low half)
__device__ __forceinline__ uint32_t bf16x2_pack(float hi, float lo) {
    uint32_t r; asm("cvt.rn.bf16x2.f32 %0, %1, %2;" : "=r"(r) : "f"(hi), "f"(lo)); return r;
}

// Ampere-class bf16 tensor-core MMA (baseline PTX; runs on sm_103 fallback HMMA)
__device__ __forceinline__ void mma_bf16(float* d, const uint32_t* a, uint32_t b0, uint32_t b1) {
    asm volatile(
        "mma.sync.aligned.m16n8k16.row.col.f32.bf16.bf16.f32 "
        "{%0,%1,%2,%3}, {%4,%5,%6,%7}, {%8,%9}, {%0,%1,%2,%3};"
        : "+f"(d[0]), "+f"(d[1]), "+f"(d[2]), "+f"(d[3])
        : "r"(a[0]), "r"(a[1]), "r"(a[2]), "r"(a[3]), "r"(b0), "r"(b1));
}

// ---------------- batched transpose: Wih1, Wih2, Wself, Wneigh ------------
__global__ void transpose_all_kernel(
    const float* __restrict__ Wih1, const float* __restrict__ Wih2,
    const float* __restrict__ Wself, const float* __restrict__ Wneigh,
    float* __restrict__ WTih1, float* __restrict__ WTih2,
    float* __restrict__ WTself, float* __restrict__ WTneigh)
{
    int i = blockIdx.x * blockDim.x + threadIdx.x;
    const float* src; float* dst; int R, local;
    if (i < 131072) {                 // two 512x128
        int seg = i >> 16; local = i & 65535; R = 512;
        src = seg ? Wih2 : Wih1; dst = seg ? WTih2 : WTih1;
    } else if (i < 163840) {          // two 128x128
        int j = i - 131072; int seg = j >> 14; local = j & 16383; R = 128;
        src = seg ? Wneigh : Wself; dst = seg ? WTneigh : WTself;
    } else return;
    int r = local >> 7, k = local & 127;
    dst[k * R + r] = src[local];
}

// ---------------- generic fused GEMM (f32x2 inner loop) ----------------
#define GEMM_SMEM ((64 * 132 + 128 * 68) * 4)
__global__ __launch_bounds__(256) void fused_gemm_kernel(
    const float* __restrict__ A,  const float* __restrict__ WT,
    const float* __restrict__ A2, const float* __restrict__ WT2,
    const float* __restrict__ b1, const float* __restrict__ b2,
    float* __restrict__ C, int Nrows, int M, int act)
{
    extern __shared__ float sm[];
    float* As = sm;
    float* Ws = sm + 64 * 132;
    int tid = threadIdx.x;
    int tx = tid & 15, ty = tid >> 4;
    int rowBase = blockIdx.y * 64, colBase = blockIdx.x * 64;

    ull acc[4][2];
#pragma unroll
    for (int i = 0; i < 4; i++) { acc[i][0] = 0ull; acc[i][1] = 0ull; }

    int npass = (A2 != nullptr) ? 2 : 1;
    for (int pass = 0; pass < npass; ++pass) {
        const float* Ap = pass ? A2 : A;
        const float* Wp = pass ? WT2 : WT;
        if (pass) __syncthreads();
        for (int f = tid; f < 64 * 32; f += 256) {
            int r = f >> 5, c4 = f & 31;
            float4 v = make_float4(0.f, 0.f, 0.f, 0.f);
            if (rowBase + r < Nrows)
                v = *(const float4*)(Ap + (size_t)(rowBase + r) * 128 + c4 * 4);
            *(float4*)(As + r * 132 + c4 * 4) = v;
        }
        for (int f = tid; f < 128 * 16; f += 256) {
            int k = f >> 4, c4 = f & 15;
            *(float4*)(Ws + k * 68 + c4 * 4) =
                *(const float4*)(Wp + (size_t)k * M + colBase + c4 * 4);
        }
        __syncthreads();
#pragma unroll 8
        for (int k = 0; k < 128; k++) {
            ulonglong2 w = *(const ulonglong2*)(Ws + k * 68 + tx * 4);
#pragma unroll
            for (int i = 0; i < 4; i++) {
                float a = As[(ty * 4 + i) * 132 + k];
                ull aa = pack2(a, a);
                acc[i][0] = fma2(aa, w.x, acc[i][0]);
                acc[i][1] = fma2(aa, w.y, acc[i][1]);
            }
        }
    }
#pragma unroll
    for (int i = 0; i < 4; i++) {
        int row = rowBase + ty * 4 + i;
        if (row < Nrows) {
            float2 v01 = unpack2(acc[i][0]);
            float2 v23 = unpack2(acc[i][1]);
            float vv[4] = {v01.x, v01.y, v23.x, v23.y};
#pragma unroll
            for (int j = 0; j < 4; j++) {
                int col = colBase + tx * 4 + j;
                float v = vv[j] + b1[col];
                if (b2) v += b2[col];
                if (act) v = fmaxf(v, 0.f);
                C[(size_t)row * M + col] = v;
            }
        }
    }
}

// ---------------- HMMA LSTM layer ----------------
// Block = 144 nodes, 9 warps (288 threads) -> grid 139 <= 148 SMs: ONE wave.
// Warp w owns node rows [16w,16w+16), all 512 gate cols.
// B fragments stored as nt-PAIRS (ulonglong2) -> one LDS.128 feeds 2 MMAs.
// A (h) is fragment-ready, double-buffered, same-lane write/read -> no
// synchronization in the 16-step main loop. Xp gathers hoisted above each
// uc's MMA loop to hide L2 latency.
#define NWARP   9
#define NODES_B (NWARP * 16)          // 144
#define SM_BF   0                      // B frag pairs: 8ks*32ntp*32lane*16B = 128KB
#define SM_AF   131072                 // A frags: 2 bufs * 9w*8ks*32lane*4slots*4B = 72KB
#define SM_IDX  (131072 + 73728)       // idx: 144*16*4 = 9216
#define LSTM_SMEM (131072 + 73728 + 9216)
__global__ void __launch_bounds__(NWARP * 32, 1) lstm_mma_kernel(
    const float* __restrict__ Xp, const int* __restrict__ nbr,
    const float* __restrict__ Whh, float* __restrict__ Hout)
{
    extern __shared__ char smem[];
    ulonglong2* Bfp  = (ulonglong2*)(smem + SM_BF);     // [ks8][ntp32][lane32]
    uint32_t*   Af   = (uint32_t*)(smem + SM_AF);       // [buf2][w9][ks8][lane32][slot4]
    int*        idx_s= (int*)(smem + SM_IDX);           // [144][16]

    const int tid = threadIdx.x;
    const int lane = tid & 31, w = tid >> 5;
    const int gr = lane >> 2, tq = lane & 3;
    const int nodeBase = blockIdx.x * NODES_B;
    const int NT = NWARP * 32;

    // ---- build fragment-pair B = Whh(n=gate_row, k=unit), bf16 ----
    // pair p covers nt = 2p, 2p+1
    for (int i = tid; i < 8192; i += NT) {       // i = ks*1024 + ntp*32 + lane
        int l = i & 31, ntp = (i >> 5) & 31, ks = i >> 10;
        int k0 = ks * 16 + 2 * (l & 3);
        ull fr[2];
#pragma unroll
        for (int h = 0; h < 2; ++h) {
            int n = (2 * ntp + h) * 8 + (l >> 2);
            const float* wr = Whh + (size_t)n * 128;
            float2 p0 = *(const float2*)(wr + k0);
            float2 p1 = *(const float2*)(wr + k0 + 8);
            uint32_t r0 = bf16x2_pack(p0.y, p0.x);
            uint32_t r1 = bf16x2_pack(p1.y, p1.x);
            fr[h] = ((ull)r1 << 32) | r0;
        }
        ulonglong2 v; v.x = fr[0]; v.y = fr[1];
        Bfp[i] = v;
    }
    // ---- neighbor indices for the whole block ----
    for (int i = tid; i < NODES_B * 16; i += NT) {
        int node = nodeBase + (i >> 4);
        idx_s[i] = (node < NNODE) ? nbr[(size_t)node * DDEG + (i & 15)] : 0;
    }
    __syncthreads();

    const int node0 = nodeBase + w * 16 + gr;
    const int node1 = node0 + 8;
    float c[4][4][4];
#pragma unroll
    for (int a = 0; a < 4; a++)
#pragma unroll
        for (int b = 0; b < 4; b++)
#pragma unroll
            for (int p = 0; p < 4; p++) c[a][b][p] = 0.f;

#pragma unroll 1
    for (int t = 0; t < DDEG; ++t) {
        const float* x0 = Xp + (size_t)idx_s[(w * 16 + gr) * DDEG + t] * 512;
        const float* x1 = Xp + (size_t)idx_s[(w * 16 + gr + 8) * DDEG + t] * 512;
        uint32_t* Ard = Af + ((t & 1) ^ 1) * (NWARP * 1024) + w * 1024;
        uint32_t* Awr = Af + (t & 1) * (NWARP * 1024) + w * 1024;

#pragma unroll
        for (int uc = 0; uc < 4; ++uc) {
            // ---- hoisted Xp gathers for this uc (hide L2 latency under MMAs)
            float2 xi0[4], xf0[4], xg0[4], xo0[4];
            float2 xi1[4], xf1[4], xg1[4], xo1[4];
#pragma unroll
            for (int j = 0; j < 4; ++j) {
                int u0 = uc * 32 + j * 8 + 2 * tq;
                xi0[j] = *(const float2*)(x0 + u0);
                xf0[j] = *(const float2*)(x0 + 128 + u0);
                xg0[j] = *(const float2*)(x0 + 256 + u0);
                xo0[j] = *(const float2*)(x0 + 384 + u0);
                xi1[j] = *(const float2*)(x1 + u0);
                xf1[j] = *(const float2*)(x1 + 128 + u0);
                xg1[j] = *(const float2*)(x1 + 256 + u0);
                xo1[j] = *(const float2*)(x1 + 384 + u0);
            }

            float d[4][4][4];                // [gate][j][p]
#pragma unroll
            for (int g = 0; g < 4; g++)
#pragma unroll
                for (int j = 0; j < 4; j++)
#pragma unroll
                    for (int p = 0; p < 4; p++) d[g][j][p] = 0.f;

            if (t > 0) {
#pragma unroll
                for (int ks = 0; ks < 8; ++ks) {
                    uint4 av = *(uint4*)(Ard + ks * 128 + lane * 4);
                    uint32_t a[4] = {av.x, av.y, av.z, av.w};
#pragma unroll
                    for (int g = 0; g < 4; ++g) {
                        int ntp0 = g * 8 + uc * 2;      // (g*16 + uc*4) / 2
#pragma unroll
                        for (int jp = 0; jp < 2; ++jp) {
                            ulonglong2 bb = Bfp[ks * 1024 + (ntp0 + jp) * 32 + lane];
                            mma_bf16(d[g][2 * jp],     a, (uint32_t)bb.x, (uint32_t)(bb.x >> 32));
                            mma_bf16(d[g][2 * jp + 1], a, (uint32_t)bb.y, (uint32_t)(bb.y >> 32));
                        }
                    }
                }
            }
            // ---- epilogue: gates + cell update for 32 units (this uc) ----
#pragma unroll
            for (int j = 0; j < 4; ++j) {
                int u0 = uc * 32 + j * 8 + 2 * tq;
                float gi[4] = {d[0][j][0] + xi0[j].x, d[0][j][1] + xi0[j].y,
                               d[0][j][2] + xi1[j].x, d[0][j][3] + xi1[j].y};
                float gf[4] = {d[1][j][0] + xf0[j].x, d[1][j][1] + xf0[j].y,
                               d[1][j][2] + xf1[j].x, d[1][j][3] + xf1[j].y};
                float gg[4] = {d[2][j][0] + xg0[j].x, d[2][j][1] + xg0[j].y,
                               d[2][j][2] + xg1[j].x, d[2][j][3] + xg1[j].y};
                float go[4] = {d[3][j][0] + xo0[j].x, d[3][j][1] + xo0[j].y,
                               d[3][j][2] + xo1[j].x, d[3][j][3] + xo1[j].y};
                float h_[4];
#pragma unroll
                for (int p = 0; p < 4; ++p) {
                    float cn = sig_f(gf[p]) * c[uc][j][p] + sig_f(gi[p]) * tanh_f(gg[p]);
                    c[uc][j][p] = cn;
                    h_[p] = sig_f(go[p]) * tanh_f(cn);
                }
                if (t < DDEG - 1) {
                    uint32_t lo = bf16x2_pack(h_[1], h_[0]);   // row r
                    uint32_t hi = bf16x2_pack(h_[3], h_[2]);   // row r+8
                    int ks = uc * 2 + (j >> 1);
                    int slot = (j & 1) * 2;
                    *(ull*)(Awr + ks * 128 + lane * 4 + slot) = ((ull)hi << 32) | lo;
                } else {
                    if (node0 < NNODE)
                        *(float2*)(Hout + (size_t)node0 * 128 + u0) = make_float2(h_[0], h_[1]);
                    if (node1 < NNODE)
                        *(float2*)(Hout + (size_t)node1 * 128 + u0) = make_float2(h_[2], h_[3]);
                }
            }
        }
    }
}

// ---------------- final layer-2 combine: OUT=1 + sigmoid ----------------
__global__ void out_kernel(const float* __restrict__ h1, const float* __restrict__ H,
                           const float* __restrict__ Wself, const float* __restrict__ Wneigh,
                           const float* __restrict__ b, float* __restrict__ out, int Nrows)
{
    int gwarp = (blockIdx.x * blockDim.x + threadIdx.x) >> 5;
    int lane = threadIdx.x & 31;
    if (gwarp >= Nrows) return;
    float s = 0.f;
#pragma unroll
    for (int q = 0; q < 4; q++) {
        int k = lane + 32 * q;
        s += h1[(size_t)gwarp * 128 + k] * Wself[k] + H[(size_t)gwarp * 128 + k] * Wneigh[k];
    }
#pragma unroll
    for (int off = 16; off; off >>= 1) s += __shfl_xor_sync(0xFFFFFFFFu, s, off);
    if (lane == 0) out[gwarp] = sig_exact(s + b[0]);
}

// ---------------- launch ----------------
extern "C" void kernel_launch(void* const* d_in, const int* in_sizes, int n_in,
                              void* d_out, int out_size)
{
    const float* x       = (const float*)d_in[0];
    const int*   nbr     = (const int*)d_in[1];
    const float* Wih1    = (const float*)d_in[2];
    const float* Whh1    = (const float*)d_in[3];
    const float* bih1    = (const float*)d_in[4];
    const float* bhh1    = (const float*)d_in[5];
    const float* Wself1  = (const float*)d_in[6];
    const float* Wneigh1 = (const float*)d_in[7];
    const float* bneigh1 = (const float*)d_in[8];
    const float* Wih2    = (const float*)d_in[9];
    const float* Whh2    = (const float*)d_in[10];
    const float* bih2    = (const float*)d_in[11];
    const float* bhh2    = (const float*)d_in[12];
    const float* Wself2  = (const float*)d_in[13];
    const float* Wneigh2 = (const float*)d_in[14];
    const float* bneigh2 = (const float*)d_in[15];
    float* out = (float*)d_out;

    float *WTih1, *WTih2, *WTself, *WTneigh, *Xp, *H, *h1;
    cudaGetSymbolAddress((void**)&WTih1,   g_WTih1);
    cudaGetSymbolAddress((void**)&WTih2,   g_WTih2);
    cudaGetSymbolAddress((void**)&WTself,  g_WTself);
    cudaGetSymbolAddress((void**)&WTneigh, g_WTneigh);
    cudaGetSymbolAddress((void**)&Xp,      g_Xp);
    cudaGetSymbolAddress((void**)&H,       g_H);
    cudaGetSymbolAddress((void**)&h1,      g_h1);

    cudaFuncSetAttribute(fused_gemm_kernel, cudaFuncAttributeMaxDynamicSharedMemorySize, GEMM_SMEM);
    cudaFuncSetAttribute(lstm_mma_kernel,   cudaFuncAttributeMaxDynamicSharedMemorySize, LSTM_SMEM);

    const int TB = 256;
    const int LSTM_GRID = (NNODE + NODES_B - 1) / NODES_B;   // 139 <= 148: one wave

    transpose_all_kernel<<<(163840 + TB - 1) / TB, TB>>>(
        Wih1, Wih2, Wself1, Wneigh1, WTih1, WTih2, WTself, WTneigh);

    // ---- layer 1 ----
    fused_gemm_kernel<<<dim3(8, 313), TB, GEMM_SMEM>>>(
        x, WTih1, nullptr, nullptr, bih1, bhh1, Xp, NNODE, 512, 0);
    lstm_mma_kernel<<<LSTM_GRID, NWARP * 32, LSTM_SMEM>>>(Xp, nbr, Whh1, H);
    fused_gemm_kernel<<<dim3(2, 313), TB, GEMM_SMEM>>>(
        x, WTself, H, WTneigh, bneigh1, nullptr, h1, NNODE, 128, 1);

    // ---- layer 2 ----
    fused_gemm_kernel<<<dim3(8, 313), TB, GEMM_SMEM>>>(
        h1, WTih2, nullptr, nullptr, bih2, bhh2, Xp, NNODE, 512, 0);
    lstm_mma_kernel<<<LSTM_GRID, NWARP * 32, LSTM_SMEM>>>(Xp, nbr, Whh2, H);
    out_kernel<<<(NNODE * 32 + TB - 1) / TB, TB>>>(h1, H, Wself2, Wneigh2, bneigh2, out, NNODE);
}

// round 14
// speedup vs baseline: 3.6874x; 1.1946x over previous
#include <cuda_runtime.h>
#include <cuda_bf16.h>
#include <cstdint>

#define NNODE 20000
#define DDEG  16

typedef unsigned long long ull;

// ---------------- scratch (device globals; no allocations) ----------------
__device__ float g_WTself[128 * 128];
__device__ float g_WTneigh[128 * 128];
__device__ float g_Xp[(size_t)NNODE * 512];   // input projection (+bias)
__device__ float g_H[(size_t)NNODE * 128];    // LSTM final hidden
__device__ float g_h1[(size_t)NNODE * 128];   // layer-1 output

// ---------------- math helpers ----------------
__device__ __forceinline__ float tanh_f(float x) {
    float y; asm("tanh.approx.f32 %0, %1;" : "=f"(y) : "f"(x)); return y;
}
__device__ __forceinline__ float sig_f(float x) {
    return fmaf(0.5f, tanh_f(0.5f * x), 0.5f);
}
__device__ __forceinline__ float sig_exact(float x) { return 1.f / (1.f + __expf(-x)); }

__device__ __forceinline__ ull fma2(ull a, ull b, ull c) {
    ull d; asm("fma.rn.f32x2 %0, %1, %2, %3;" : "=l"(d) : "l"(a), "l"(b), "l"(c)); return d;
}
__device__ __forceinline__ ull pack2(float x, float y) {
    ull d; asm("mov.b64 %0, {%1, %2};" : "=l"(d) : "f"(x), "f"(y)); return d;
}
__device__ __forceinline__ float2 unpack2(ull v) {
    float2 r; asm("mov.b64 {%0, %1}, %2;" : "=f"(r.x), "=f"(r.y) : "l"(v)); return r;
}
// pack two fp32 -> bf16x2 (lo in low half)
__device__ __forceinline__ uint32_t bf16x2_pack(float hi, float lo) {
    uint32_t r; asm("cvt.rn.bf16x2.f32 %0, %1, %2;" : "=r"(r) : "f"(hi), "f"(lo)); return r;
}

// Ampere-class bf16 tensor-core MMA (baseline PTX; runs on sm_103 fallback HMMA)
__device__ __forceinline__ void mma_bf16(float* d, const uint32_t* a, uint32_t b0, uint32_t b1) {
    asm volatile(
        "mma.sync.aligned.m16n8k16.row.col.f32.bf16.bf16.f32 "
        "{%0,%1,%2,%3}, {%4,%5,%6,%7}, {%8,%9}, {%0,%1,%2,%3};"
        : "+f"(d[0]), "+f"(d[1]), "+f"(d[2]), "+f"(d[3])
        : "r"(a[0]), "r"(a[1]), "r"(a[2]), "r"(a[3]), "r"(b0), "r"(b1));
}

#define NWARP   9
#define NODES_B (NWARP * 16)          // 144

// ---------------- small transpose: Wself, Wneigh (128x128 each) -----------
__global__ void transpose_small_kernel(
    const float* __restrict__ Wself, const float* __restrict__ Wneigh,
    float* __restrict__ WTself, float* __restrict__ WTneigh)
{
    int i = blockIdx.x * blockDim.x + threadIdx.x;
    if (i >= 32768) return;
    int seg = i >> 14, local = i & 16383;
    const float* src = seg ? Wneigh : Wself;
    float* dst = seg ? WTneigh : WTself;
    int r = local >> 7, k = local & 127;
    dst[k * 128 + r] = src[local];
}

// ---------------- HMMA projection GEMM ----------------
// Xp[N,512] = bf16(A[N,128]) @ bf16(Wih[512,128])^T + (bih+bhh)
// Block = 144 rows, 9 warps, one wave (139 blocks). Warp: 16 rows x 512 cols.
// B packed once per block into nt-pair fragments; A fragments straight from
// global into registers (reused across all 64 nt per ks).
#define PROJ_SMEM (131072 + 2048)
__global__ void __launch_bounds__(NWARP * 32, 1) hmma_proj_kernel(
    const float* __restrict__ A, const float* __restrict__ Wih,
    const float* __restrict__ bih, const float* __restrict__ bhh,
    float* __restrict__ Xp)
{
    extern __shared__ char smem[];
    ulonglong2* Bfp  = (ulonglong2*)smem;              // [ks8][ntp32][lane32]
    float*      bsum = (float*)(smem + 131072);        // [512]

    const int tid = threadIdx.x;
    const int lane = tid & 31, w = tid >> 5;
    const int gr = lane >> 2, tq = lane & 3;
    const int NT = NWARP * 32;

    // ---- pack B = Wih (row-major [n=512][k=128]) into pair fragments ----
    for (int i = tid; i < 8192; i += NT) {       // i = ks*1024 + ntp*32 + lane
        int l = i & 31, ntp = (i >> 5) & 31, ks = i >> 10;
        int k0 = ks * 16 + 2 * (l & 3);
        ull fr[2];
#pragma unroll
        for (int h = 0; h < 2; ++h) {
            int n = (2 * ntp + h) * 8 + (l >> 2);
            const float* wr = Wih + (size_t)n * 128;
            float2 p0 = *(const float2*)(wr + k0);
            float2 p1 = *(const float2*)(wr + k0 + 8);
            fr[h] = ((ull)bf16x2_pack(p1.y, p1.x) << 32) | bf16x2_pack(p0.y, p0.x);
        }
        ulonglong2 v; v.x = fr[0]; v.y = fr[1];
        Bfp[i] = v;
    }
    for (int i = tid; i < 512; i += NT) bsum[i] = bih[i] + bhh[i];
    __syncthreads();

    const int r0 = blockIdx.x * NODES_B + w * 16 + gr;
    const int r1 = r0 + 8;
    const float* a0 = A + (size_t)((r0 < NNODE) ? r0 : NNODE - 1) * 128;
    const float* a1 = A + (size_t)((r1 < NNODE) ? r1 : NNODE - 1) * 128;

    // ---- A fragments in registers (bf16) ----
    uint32_t a[8][4];
#pragma unroll
    for (int ks = 0; ks < 8; ++ks) {
        int k0 = ks * 16 + 2 * tq;
        float2 q;
        q = *(const float2*)(a0 + k0);     a[ks][0] = bf16x2_pack(q.y, q.x);
        q = *(const float2*)(a1 + k0);     a[ks][1] = bf16x2_pack(q.y, q.x);
        q = *(const float2*)(a0 + k0 + 8); a[ks][2] = bf16x2_pack(q.y, q.x);
        q = *(const float2*)(a1 + k0 + 8); a[ks][3] = bf16x2_pack(q.y, q.x);
    }

#pragma unroll
    for (int c = 0; c < 8; ++c) {            // 64-col chunks
        float d[8][4];
#pragma unroll
        for (int m = 0; m < 8; m++)
#pragma unroll
            for (int p = 0; p < 4; p++) d[m][p] = 0.f;
#pragma unroll
        for (int ks = 0; ks < 8; ++ks) {
#pragma unroll
            for (int jp = 0; jp < 4; ++jp) {
                ulonglong2 bb = Bfp[ks * 1024 + (c * 4 + jp) * 32 + lane];
                mma_bf16(d[2 * jp],     a[ks], (uint32_t)bb.x, (uint32_t)(bb.x >> 32));
                mma_bf16(d[2 * jp + 1], a[ks], (uint32_t)bb.y, (uint32_t)(bb.y >> 32));
            }
        }
#pragma unroll
        for (int m = 0; m < 8; ++m) {
            int col = c * 64 + m * 8 + 2 * tq;
            float2 bv = *(const float2*)(bsum + col);
            if (r0 < NNODE)
                *(float2*)(Xp + (size_t)r0 * 512 + col) = make_float2(d[m][0] + bv.x, d[m][1] + bv.y);
            if (r1 < NNODE)
                *(float2*)(Xp + (size_t)r1 * 512 + col) = make_float2(d[m][2] + bv.x, d[m][3] + bv.y);
        }
    }
}

// ---------------- generic fused GEMM (f32x2) — layer-1 combine only -------
#define GEMM_SMEM ((64 * 132 + 128 * 68) * 4)
__global__ __launch_bounds__(256) void fused_gemm_kernel(
    const float* __restrict__ A,  const float* __restrict__ WT,
    const float* __restrict__ A2, const float* __restrict__ WT2,
    const float* __restrict__ b1,
    float* __restrict__ C, int Nrows, int M, int act)
{
    extern __shared__ float sm[];
    float* As = sm;
    float* Ws = sm + 64 * 132;
    int tid = threadIdx.x;
    int tx = tid & 15, ty = tid >> 4;
    int rowBase = blockIdx.y * 64, colBase = blockIdx.x * 64;

    ull acc[4][2];
#pragma unroll
    for (int i = 0; i < 4; i++) { acc[i][0] = 0ull; acc[i][1] = 0ull; }

    int npass = (A2 != nullptr) ? 2 : 1;
    for (int pass = 0; pass < npass; ++pass) {
        const float* Ap = pass ? A2 : A;
        const float* Wp = pass ? WT2 : WT;
        if (pass) __syncthreads();
        for (int f = tid; f < 64 * 32; f += 256) {
            int r = f >> 5, c4 = f & 31;
            float4 v = make_float4(0.f, 0.f, 0.f, 0.f);
            if (rowBase + r < Nrows)
                v = *(const float4*)(Ap + (size_t)(rowBase + r) * 128 + c4 * 4);
            *(float4*)(As + r * 132 + c4 * 4) = v;
        }
        for (int f = tid; f < 128 * 16; f += 256) {
            int k = f >> 4, c4 = f & 15;
            *(float4*)(Ws + k * 68 + c4 * 4) =
                *(const float4*)(Wp + (size_t)k * M + colBase + c4 * 4);
        }
        __syncthreads();
#pragma unroll 8
        for (int k = 0; k < 128; k++) {
            ulonglong2 w = *(const ulonglong2*)(Ws + k * 68 + tx * 4);
#pragma unroll
            for (int i = 0; i < 4; i++) {
                float a = As[(ty * 4 + i) * 132 + k];
                ull aa = pack2(a, a);
                acc[i][0] = fma2(aa, w.x, acc[i][0]);
                acc[i][1] = fma2(aa, w.y, acc[i][1]);
            }
        }
    }
#pragma unroll
    for (int i = 0; i < 4; i++) {
        int row = rowBase + ty * 4 + i;
        if (row < Nrows) {
            float2 v01 = unpack2(acc[i][0]);
            float2 v23 = unpack2(acc[i][1]);
            float vv[4] = {v01.x, v01.y, v23.x, v23.y};
#pragma unroll
            for (int j = 0; j < 4; j++) {
                int col = colBase + tx * 4 + j;
                float v = vv[j] + b1[col];
                if (act) v = fmaxf(v, 0.f);
                C[(size_t)row * M + col] = v;
            }
        }
    }
}

// ---------------- HMMA LSTM layer (unchanged from R13) ----------------
#define SM_BF   0
#define SM_AF   131072
#define SM_IDX  (131072 + 73728)
#define LSTM_SMEM (131072 + 73728 + 9216)
__global__ void __launch_bounds__(NWARP * 32, 1) lstm_mma_kernel(
    const float* __restrict__ Xp, const int* __restrict__ nbr,
    const float* __restrict__ Whh, float* __restrict__ Hout)
{
    extern __shared__ char smem[];
    ulonglong2* Bfp  = (ulonglong2*)(smem + SM_BF);
    uint32_t*   Af   = (uint32_t*)(smem + SM_AF);
    int*        idx_s= (int*)(smem + SM_IDX);

    const int tid = threadIdx.x;
    const int lane = tid & 31, w = tid >> 5;
    const int gr = lane >> 2, tq = lane & 3;
    const int nodeBase = blockIdx.x * NODES_B;
    const int NT = NWARP * 32;

    for (int i = tid; i < 8192; i += NT) {
        int l = i & 31, ntp = (i >> 5) & 31, ks = i >> 10;
        int k0 = ks * 16 + 2 * (l & 3);
        ull fr[2];
#pragma unroll
        for (int h = 0; h < 2; ++h) {
            int n = (2 * ntp + h) * 8 + (l >> 2);
            const float* wr = Whh + (size_t)n * 128;
            float2 p0 = *(const float2*)(wr + k0);
            float2 p1 = *(const float2*)(wr + k0 + 8);
            fr[h] = ((ull)bf16x2_pack(p1.y, p1.x) << 32) | bf16x2_pack(p0.y, p0.x);
        }
        ulonglong2 v; v.x = fr[0]; v.y = fr[1];
        Bfp[i] = v;
    }
    for (int i = tid; i < NODES_B * 16; i += NT) {
        int node = nodeBase + (i >> 4);
        idx_s[i] = (node < NNODE) ? nbr[(size_t)node * DDEG + (i & 15)] : 0;
    }
    __syncthreads();

    const int node0 = nodeBase + w * 16 + gr;
    const int node1 = node0 + 8;
    float c[4][4][4];
#pragma unroll
    for (int a = 0; a < 4; a++)
#pragma unroll
        for (int b = 0; b < 4; b++)
#pragma unroll
            for (int p = 0; p < 4; p++) c[a][b][p] = 0.f;

#pragma unroll 1
    for (int t = 0; t < DDEG; ++t) {
        const float* x0 = Xp + (size_t)idx_s[(w * 16 + gr) * DDEG + t] * 512;
        const float* x1 = Xp + (size_t)idx_s[(w * 16 + gr + 8) * DDEG + t] * 512;
        uint32_t* Ard = Af + ((t & 1) ^ 1) * (NWARP * 1024) + w * 1024;
        uint32_t* Awr = Af + (t & 1) * (NWARP * 1024) + w * 1024;

#pragma unroll
        for (int uc = 0; uc < 4; ++uc) {
            float2 xi0[4], xf0[4], xg0[4], xo0[4];
            float2 xi1[4], xf1[4], xg1[4], xo1[4];
#pragma unroll
            for (int j = 0; j < 4; ++j) {
                int u0 = uc * 32 + j * 8 + 2 * tq;
                xi0[j] = *(const float2*)(x0 + u0);
                xf0[j] = *(const float2*)(x0 + 128 + u0);
                xg0[j] = *(const float2*)(x0 + 256 + u0);
                xo0[j] = *(const float2*)(x0 + 384 + u0);
                xi1[j] = *(const float2*)(x1 + u0);
                xf1[j] = *(const float2*)(x1 + 128 + u0);
                xg1[j] = *(const float2*)(x1 + 256 + u0);
                xo1[j] = *(const float2*)(x1 + 384 + u0);
            }

            float d[4][4][4];
#pragma unroll
            for (int g = 0; g < 4; g++)
#pragma unroll
                for (int j = 0; j < 4; j++)
#pragma unroll
                    for (int p = 0; p < 4; p++) d[g][j][p] = 0.f;

            if (t > 0) {
#pragma unroll
                for (int ks = 0; ks < 8; ++ks) {
                    uint4 av = *(uint4*)(Ard + ks * 128 + lane * 4);
                    uint32_t a[4] = {av.x, av.y, av.z, av.w};
#pragma unroll
                    for (int g = 0; g < 4; ++g) {
                        int ntp0 = g * 8 + uc * 2;
#pragma unroll
                        for (int jp = 0; jp < 2; ++jp) {
                            ulonglong2 bb = Bfp[ks * 1024 + (ntp0 + jp) * 32 + lane];
                            mma_bf16(d[g][2 * jp],     a, (uint32_t)bb.x, (uint32_t)(bb.x >> 32));
                            mma_bf16(d[g][2 * jp + 1], a, (uint32_t)bb.y, (uint32_t)(bb.y >> 32));
                        }
                    }
                }
            }
#pragma unroll
            for (int j = 0; j < 4; ++j) {
                int u0 = uc * 32 + j * 8 + 2 * tq;
                float gi[4] = {d[0][j][0] + xi0[j].x, d[0][j][1] + xi0[j].y,
                               d[0][j][2] + xi1[j].x, d[0][j][3] + xi1[j].y};
                float gf[4] = {d[1][j][0] + xf0[j].x, d[1][j][1] + xf0[j].y,
                               d[1][j][2] + xf1[j].x, d[1][j][3] + xf1[j].y};
                float gg[4] = {d[2][j][0] + xg0[j].x, d[2][j][1] + xg0[j].y,
                               d[2][j][2] + xg1[j].x, d[2][j][3] + xg1[j].y};
                float go[4] = {d[3][j][0] + xo0[j].x, d[3][j][1] + xo0[j].y,
                               d[3][j][2] + xo1[j].x, d[3][j][3] + xo1[j].y};
                float h_[4];
#pragma unroll
                for (int p = 0; p < 4; ++p) {
                    float cn = sig_f(gf[p]) * c[uc][j][p] + sig_f(gi[p]) * tanh_f(gg[p]);
                    c[uc][j][p] = cn;
                    h_[p] = sig_f(go[p]) * tanh_f(cn);
                }
                if (t < DDEG - 1) {
                    uint32_t lo = bf16x2_pack(h_[1], h_[0]);
                    uint32_t hi = bf16x2_pack(h_[3], h_[2]);
                    int ks = uc * 2 + (j >> 1);
                    int slot = (j & 1) * 2;
                    *(ull*)(Awr + ks * 128 + lane * 4 + slot) = ((ull)hi << 32) | lo;
                } else {
                    if (node0 < NNODE)
                        *(float2*)(Hout + (size_t)node0 * 128 + u0) = make_float2(h_[0], h_[1]);
                    if (node1 < NNODE)
                        *(float2*)(Hout + (size_t)node1 * 128 + u0) = make_float2(h_[2], h_[3]);
                }
            }
        }
    }
}

// ---------------- final layer-2 combine: OUT=1 + sigmoid ----------------
__global__ void out_kernel(const float* __restrict__ h1, const float* __restrict__ H,
                           const float* __restrict__ Wself, const float* __restrict__ Wneigh,
                           const float* __restrict__ b, float* __restrict__ out, int Nrows)
{
    int gwarp = (blockIdx.x * blockDim.x + threadIdx.x) >> 5;
    int lane = threadIdx.x & 31;
    if (gwarp >= Nrows) return;
    float s = 0.f;
#pragma unroll
    for (int q = 0; q < 4; q++) {
        int k = lane + 32 * q;
        s += h1[(size_t)gwarp * 128 + k] * Wself[k] + H[(size_t)gwarp * 128 + k] * Wneigh[k];
    }
#pragma unroll
    for (int off = 16; off; off >>= 1) s += __shfl_xor_sync(0xFFFFFFFFu, s, off);
    if (lane == 0) out[gwarp] = sig_exact(s + b[0]);
}

// ---------------- launch ----------------
extern "C" void kernel_launch(void* const* d_in, const int* in_sizes, int n_in,
                              void* d_out, int out_size)
{
    const float* x       = (const float*)d_in[0];
    const int*   nbr     = (const int*)d_in[1];
    const float* Wih1    = (const float*)d_in[2];
    const float* Whh1    = (const float*)d_in[3];
    const float* bih1    = (const float*)d_in[4];
    const float* bhh1    = (const float*)d_in[5];
    const float* Wself1  = (const float*)d_in[6];
    const float* Wneigh1 = (const float*)d_in[7];
    const float* bneigh1 = (const float*)d_in[8];
    const float* Wih2    = (const float*)d_in[9];
    const float* Whh2    = (const float*)d_in[10];
    const float* bih2    = (const float*)d_in[11];
    const float* bhh2    = (const float*)d_in[12];
    const float* Wself2  = (const float*)d_in[13];
    const float* Wneigh2 = (const float*)d_in[14];
    const float* bneigh2 = (const float*)d_in[15];
    float* out = (float*)d_out;

    float *WTself, *WTneigh, *Xp, *H, *h1;
    cudaGetSymbolAddress((void**)&WTself,  g_WTself);
    cudaGetSymbolAddress((void**)&WTneigh, g_WTneigh);
    cudaGetSymbolAddress((void**)&Xp,      g_Xp);
    cudaGetSymbolAddress((void**)&H,       g_H);
    cudaGetSymbolAddress((void**)&h1,      g_h1);

    cudaFuncSetAttribute(fused_gemm_kernel, cudaFuncAttributeMaxDynamicSharedMemorySize, GEMM_SMEM);
    cudaFuncSetAttribute(lstm_mma_kernel,   cudaFuncAttributeMaxDynamicSharedMemorySize, LSTM_SMEM);
    cudaFuncSetAttribute(hmma_proj_kernel,  cudaFuncAttributeMaxDynamicSharedMemorySize, PROJ_SMEM);

    const int TB = 256;
    const int GRID = (NNODE + NODES_B - 1) / NODES_B;   // 139 <= 148: one wave

    transpose_small_kernel<<<(32768 + TB - 1) / TB, TB>>>(Wself1, Wneigh1, WTself, WTneigh);

    // ---- layer 1 ----
    hmma_proj_kernel<<<GRID, NWARP * 32, PROJ_SMEM>>>(x, Wih1, bih1, bhh1, Xp);
    lstm_mma_kernel<<<GRID, NWARP * 32, LSTM_SMEM>>>(Xp, nbr, Whh1, H);
    fused_gemm_kernel<<<dim3(2, 313), TB, GEMM_SMEM>>>(
        x, WTself, H, WTneigh, bneigh1, h1, NNODE, 128, 1);

    // ---- layer 2 ----
    hmma_proj_kernel<<<GRID, NWARP * 32, PROJ_SMEM>>>(h1, Wih2, bih2, bhh2, Xp);
    lstm_mma_kernel<<<GRID, NWARP * 32, LSTM_SMEM>>>(Xp, nbr, Whh2, H);
    out_kernel<<<(NNODE * 32 + TB - 1) / TB, TB>>>(h1, H, Wself2, Wneigh2, bneigh2, out, NNODE);
}

// round 15
// speedup vs baseline: 4.1501x; 1.1255x over previous
#include <cuda_runtime.h>
#include <cuda_bf16.h>
#include <cuda_fp16.h>
#include <cstdint>

#define NNODE 20000
#define DDEG  16

typedef unsigned long long ull;

// ---------------- scratch (device globals; no allocations) ----------------
__device__ __half g_Xp[(size_t)NNODE * 512];  // input projection (+bias), fp16
__device__ float  g_H[(size_t)NNODE * 128];   // LSTM final hidden
__device__ float  g_h1[(size_t)NNODE * 128];  // layer-1 output

// ---------------- math helpers ----------------
__device__ __forceinline__ float tanh_f(float x) {
    float y; asm("tanh.approx.f32 %0, %1;" : "=f"(y) : "f"(x)); return y;
}
__device__ __forceinline__ float sig_f(float x) {
    return fmaf(0.5f, tanh_f(0.5f * x), 0.5f);
}
__device__ __forceinline__ float sig_exact(float x) { return 1.f / (1.f + __expf(-x)); }

// pack two fp32 -> bf16x2 (lo in low half)
__device__ __forceinline__ uint32_t bf16x2_pack(float hi, float lo) {
    uint32_t r; asm("cvt.rn.bf16x2.f32 %0, %1, %2;" : "=r"(r) : "f"(hi), "f"(lo)); return r;
}

// Ampere-class bf16 tensor-core MMA (baseline PTX; runs on sm_103 fallback HMMA)
__device__ __forceinline__ void mma_bf16(float* d, const uint32_t* a, uint32_t b0, uint32_t b1) {
    asm volatile(
        "mma.sync.aligned.m16n8k16.row.col.f32.bf16.bf16.f32 "
        "{%0,%1,%2,%3}, {%4,%5,%6,%7}, {%8,%9}, {%0,%1,%2,%3};"
        : "+f"(d[0]), "+f"(d[1]), "+f"(d[2]), "+f"(d[3])
        : "r"(a[0]), "r"(a[1]), "r"(a[2]), "r"(a[3]), "r"(b0), "r"(b1));
}

#define NWARP   9
#define NODES_B (NWARP * 16)          // 144

// ---------------- HMMA projection GEMM ----------------
// Xp[N,512] = fp16( bf16(A[N,128]) @ bf16(Wih[512,128])^T + (bih+bhh) )
#define PROJ_SMEM (131072 + 2048)
__global__ void __launch_bounds__(NWARP * 32, 1) hmma_proj_kernel(
    const float* __restrict__ A, const float* __restrict__ Wih,
    const float* __restrict__ bih, const float* __restrict__ bhh,
    __half* __restrict__ Xp)
{
    extern __shared__ char smem[];
    ulonglong2* Bfp  = (ulonglong2*)smem;              // [ks8][ntp32][lane32]
    float*      bsum = (float*)(smem + 131072);        // [512]

    const int tid = threadIdx.x;
    const int lane = tid & 31, w = tid >> 5;
    const int gr = lane >> 2, tq = lane & 3;
    const int NT = NWARP * 32;

    for (int i = tid; i < 8192; i += NT) {       // i = ks*1024 + ntp*32 + lane
        int l = i & 31, ntp = (i >> 5) & 31, ks = i >> 10;
        int k0 = ks * 16 + 2 * (l & 3);
        ull fr[2];
#pragma unroll
        for (int h = 0; h < 2; ++h) {
            int n = (2 * ntp + h) * 8 + (l >> 2);
            const float* wr = Wih + (size_t)n * 128;
            float2 p0 = *(const float2*)(wr + k0);
            float2 p1 = *(const float2*)(wr + k0 + 8);
            fr[h] = ((ull)bf16x2_pack(p1.y, p1.x) << 32) | bf16x2_pack(p0.y, p0.x);
        }
        ulonglong2 v; v.x = fr[0]; v.y = fr[1];
        Bfp[i] = v;
    }
    for (int i = tid; i < 512; i += NT) bsum[i] = bih[i] + bhh[i];
    __syncthreads();

    const int r0 = blockIdx.x * NODES_B + w * 16 + gr;
    const int r1 = r0 + 8;
    const float* a0 = A + (size_t)((r0 < NNODE) ? r0 : NNODE - 1) * 128;
    const float* a1 = A + (size_t)((r1 < NNODE) ? r1 : NNODE - 1) * 128;

    uint32_t a[8][4];
#pragma unroll
    for (int ks = 0; ks < 8; ++ks) {
        int k0 = ks * 16 + 2 * tq;
        float2 q;
        q = *(const float2*)(a0 + k0);     a[ks][0] = bf16x2_pack(q.y, q.x);
        q = *(const float2*)(a1 + k0);     a[ks][1] = bf16x2_pack(q.y, q.x);
        q = *(const float2*)(a0 + k0 + 8); a[ks][2] = bf16x2_pack(q.y, q.x);
        q = *(const float2*)(a1 + k0 + 8); a[ks][3] = bf16x2_pack(q.y, q.x);
    }

#pragma unroll
    for (int c = 0; c < 8; ++c) {            // 64-col chunks
        float d[8][4];
#pragma unroll
        for (int m = 0; m < 8; m++)
#pragma unroll
            for (int p = 0; p < 4; p++) d[m][p] = 0.f;
#pragma unroll
        for (int ks = 0; ks < 8; ++ks) {
#pragma unroll
            for (int jp = 0; jp < 4; ++jp) {
                ulonglong2 bb = Bfp[ks * 1024 + (c * 4 + jp) * 32 + lane];
                mma_bf16(d[2 * jp],     a[ks], (uint32_t)bb.x, (uint32_t)(bb.x >> 32));
                mma_bf16(d[2 * jp + 1], a[ks], (uint32_t)bb.y, (uint32_t)(bb.y >> 32));
            }
        }
#pragma unroll
        for (int m = 0; m < 8; ++m) {
            int col = c * 64 + m * 8 + 2 * tq;
            float2 bv = *(const float2*)(bsum + col);
            if (r0 < NNODE)
                *(__half2*)(Xp + (size_t)r0 * 512 + col) =
                    __floats2half2_rn(d[m][0] + bv.x, d[m][1] + bv.y);
            if (r1 < NNODE)
                *(__half2*)(Xp + (size_t)r1 * 512 + col) =
                    __floats2half2_rn(d[m][2] + bv.x, d[m][3] + bv.y);
        }
    }
}

// ---------------- HMMA combine: h1 = relu(x@Wself^T + H@Wneigh^T + b) -----
// One wave, 144 rows/block, N=128, two (A,B) passes accumulated in fp32.
#define CMB_SMEM (65536 + 512)
__global__ void __launch_bounds__(NWARP * 32, 1) hmma_combine_kernel(
    const float* __restrict__ x, const float* __restrict__ H,
    const float* __restrict__ Wself, const float* __restrict__ Wneigh,
    const float* __restrict__ b, float* __restrict__ h1)
{
    extern __shared__ char smem[];
    ulonglong2* Bfp  = (ulonglong2*)smem;              // [set2][ks8][ntp8][lane32]
    float*      bs   = (float*)(smem + 65536);         // [128]

    const int tid = threadIdx.x;
    const int lane = tid & 31, w = tid >> 5;
    const int gr = lane >> 2, tq = lane & 3;
    const int NT = NWARP * 32;

    for (int i = tid; i < 4096; i += NT) {   // set*2048 + ks*256 + ntp*32 + lane
        int set = i >> 11, rem = i & 2047;
        int ks = rem >> 8, ntp = (rem >> 5) & 7, l = rem & 31;
        const float* W = set ? Wneigh : Wself;
        int k0 = ks * 16 + 2 * (l & 3);
        ull fr[2];
#pragma unroll
        for (int h = 0; h < 2; ++h) {
            int n = (2 * ntp + h) * 8 + (l >> 2);
            const float* wr = W + (size_t)n * 128;
            float2 p0 = *(const float2*)(wr + k0);
            float2 p1 = *(const float2*)(wr + k0 + 8);
            fr[h] = ((ull)bf16x2_pack(p1.y, p1.x) << 32) | bf16x2_pack(p0.y, p0.x);
        }
        ulonglong2 v; v.x = fr[0]; v.y = fr[1];
        Bfp[i] = v;
    }
    for (int i = tid; i < 128; i += NT) bs[i] = b[i];
    __syncthreads();

    const int r0 = blockIdx.x * NODES_B + w * 16 + gr;
    const int r1 = r0 + 8;
    const int cr0 = (r0 < NNODE) ? r0 : NNODE - 1;
    const int cr1 = (r1 < NNODE) ? r1 : NNODE - 1;

    float d[16][4];
#pragma unroll
    for (int m = 0; m < 16; m++)
#pragma unroll
        for (int p = 0; p < 4; p++) d[m][p] = 0.f;

#pragma unroll
    for (int pass = 0; pass < 2; ++pass) {
        const float* A = pass ? H : x;
        const float* a0 = A + (size_t)cr0 * 128;
        const float* a1 = A + (size_t)cr1 * 128;
        uint32_t a[8][4];
#pragma unroll
        for (int ks = 0; ks < 8; ++ks) {
            int k0 = ks * 16 + 2 * tq;
            float2 q;
            q = *(const float2*)(a0 + k0);     a[ks][0] = bf16x2_pack(q.y, q.x);
            q = *(const float2*)(a1 + k0);     a[ks][1] = bf16x2_pack(q.y, q.x);
            q = *(const float2*)(a0 + k0 + 8); a[ks][2] = bf16x2_pack(q.y, q.x);
            q = *(const float2*)(a1 + k0 + 8); a[ks][3] = bf16x2_pack(q.y, q.x);
        }
#pragma unroll
        for (int ks = 0; ks < 8; ++ks) {
#pragma unroll
            for (int jp = 0; jp < 8; ++jp) {
                ulonglong2 bb = Bfp[pass * 2048 + ks * 256 + jp * 32 + lane];
                mma_bf16(d[2 * jp],     a[ks], (uint32_t)bb.x, (uint32_t)(bb.x >> 32));
                mma_bf16(d[2 * jp + 1], a[ks], (uint32_t)bb.y, (uint32_t)(bb.y >> 32));
            }
        }
    }
#pragma unroll
    for (int m = 0; m < 16; ++m) {
        int col = m * 8 + 2 * tq;
        float2 bv = *(const float2*)(bs + col);
        if (r0 < NNODE)
            *(float2*)(h1 + (size_t)r0 * 128 + col) =
                make_float2(fmaxf(d[m][0] + bv.x, 0.f), fmaxf(d[m][1] + bv.y, 0.f));
        if (r1 < NNODE)
            *(float2*)(h1 + (size_t)r1 * 128 + col) =
                make_float2(fmaxf(d[m][2] + bv.x, 0.f), fmaxf(d[m][3] + bv.y, 0.f));
    }
}

// ---------------- HMMA LSTM layer (fp16 Xp gathers) ----------------
#define SM_BF   0
#define SM_AF   131072
#define SM_IDX  (131072 + 73728)
#define LSTM_SMEM (131072 + 73728 + 9216)
__global__ void __launch_bounds__(NWARP * 32, 1) lstm_mma_kernel(
    const __half* __restrict__ Xp, const int* __restrict__ nbr,
    const float* __restrict__ Whh, float* __restrict__ Hout)
{
    extern __shared__ char smem[];
    ulonglong2* Bfp  = (ulonglong2*)(smem + SM_BF);
    uint32_t*   Af   = (uint32_t*)(smem + SM_AF);
    int*        idx_s= (int*)(smem + SM_IDX);

    const int tid = threadIdx.x;
    const int lane = tid & 31, w = tid >> 5;
    const int gr = lane >> 2, tq = lane & 3;
    const int nodeBase = blockIdx.x * NODES_B;
    const int NT = NWARP * 32;

    for (int i = tid; i < 8192; i += NT) {
        int l = i & 31, ntp = (i >> 5) & 31, ks = i >> 10;
        int k0 = ks * 16 + 2 * (l & 3);
        ull fr[2];
#pragma unroll
        for (int h = 0; h < 2; ++h) {
            int n = (2 * ntp + h) * 8 + (l >> 2);
            const float* wr = Whh + (size_t)n * 128;
            float2 p0 = *(const float2*)(wr + k0);
            float2 p1 = *(const float2*)(wr + k0 + 8);
            fr[h] = ((ull)bf16x2_pack(p1.y, p1.x) << 32) | bf16x2_pack(p0.y, p0.x);
        }
        ulonglong2 v; v.x = fr[0]; v.y = fr[1];
        Bfp[i] = v;
    }
    for (int i = tid; i < NODES_B * 16; i += NT) {
        int node = nodeBase + (i >> 4);
        idx_s[i] = (node < NNODE) ? nbr[(size_t)node * DDEG + (i & 15)] : 0;
    }
    __syncthreads();

    const int node0 = nodeBase + w * 16 + gr;
    const int node1 = node0 + 8;
    float c[4][4][4];
#pragma unroll
    for (int a = 0; a < 4; a++)
#pragma unroll
        for (int b = 0; b < 4; b++)
#pragma unroll
            for (int p = 0; p < 4; p++) c[a][b][p] = 0.f;

#pragma unroll 1
    for (int t = 0; t < DDEG; ++t) {
        const __half* x0 = Xp + (size_t)idx_s[(w * 16 + gr) * DDEG + t] * 512;
        const __half* x1 = Xp + (size_t)idx_s[(w * 16 + gr + 8) * DDEG + t] * 512;
        uint32_t* Ard = Af + ((t & 1) ^ 1) * (NWARP * 1024) + w * 1024;
        uint32_t* Awr = Af + (t & 1) * (NWARP * 1024) + w * 1024;

#pragma unroll
        for (int uc = 0; uc < 4; ++uc) {
            __half2 xi0[4], xf0[4], xg0[4], xo0[4];
            __half2 xi1[4], xf1[4], xg1[4], xo1[4];
#pragma unroll
            for (int j = 0; j < 4; ++j) {
                int u0 = uc * 32 + j * 8 + 2 * tq;
                xi0[j] = *(const __half2*)(x0 + u0);
                xf0[j] = *(const __half2*)(x0 + 128 + u0);
                xg0[j] = *(const __half2*)(x0 + 256 + u0);
                xo0[j] = *(const __half2*)(x0 + 384 + u0);
                xi1[j] = *(const __half2*)(x1 + u0);
                xf1[j] = *(const __half2*)(x1 + 128 + u0);
                xg1[j] = *(const __half2*)(x1 + 256 + u0);
                xo1[j] = *(const __half2*)(x1 + 384 + u0);
            }

            float d[4][4][4];
#pragma unroll
            for (int g = 0; g < 4; g++)
#pragma unroll
                for (int j = 0; j < 4; j++)
#pragma unroll
                    for (int p = 0; p < 4; p++) d[g][j][p] = 0.f;

            if (t > 0) {
#pragma unroll
                for (int ks = 0; ks < 8; ++ks) {
                    uint4 av = *(uint4*)(Ard + ks * 128 + lane * 4);
                    uint32_t a[4] = {av.x, av.y, av.z, av.w};
#pragma unroll
                    for (int g = 0; g < 4; ++g) {
                        int ntp0 = g * 8 + uc * 2;
#pragma unroll
                        for (int jp = 0; jp < 2; ++jp) {
                            ulonglong2 bb = Bfp[ks * 1024 + (ntp0 + jp) * 32 + lane];
                            mma_bf16(d[g][2 * jp],     a, (uint32_t)bb.x, (uint32_t)(bb.x >> 32));
                            mma_bf16(d[g][2 * jp + 1], a, (uint32_t)bb.y, (uint32_t)(bb.y >> 32));
                        }
                    }
                }
            }
#pragma unroll
            for (int j = 0; j < 4; ++j) {
                int u0 = uc * 32 + j * 8 + 2 * tq;
                float2 vi0 = __half22float2(xi0[j]), vi1 = __half22float2(xi1[j]);
                float2 vf0 = __half22float2(xf0[j]), vf1 = __half22float2(xf1[j]);
                float2 vg0 = __half22float2(xg0[j]), vg1 = __half22float2(xg1[j]);
                float2 vo0 = __half22float2(xo0[j]), vo1 = __half22float2(xo1[j]);
                float gi[4] = {d[0][j][0] + vi0.x, d[0][j][1] + vi0.y,
                               d[0][j][2] + vi1.x, d[0][j][3] + vi1.y};
                float gf[4] = {d[1][j][0] + vf0.x, d[1][j][1] + vf0.y,
                               d[1][j][2] + vf1.x, d[1][j][3] + vf1.y};
                float gg[4] = {d[2][j][0] + vg0.x, d[2][j][1] + vg0.y,
                               d[2][j][2] + vg1.x, d[2][j][3] + vg1.y};
                float go[4] = {d[3][j][0] + vo0.x, d[3][j][1] + vo0.y,
                               d[3][j][2] + vo1.x, d[3][j][3] + vo1.y};
                float h_[4];
#pragma unroll
                for (int p = 0; p < 4; ++p) {
                    float cn = sig_f(gf[p]) * c[uc][j][p] + sig_f(gi[p]) * tanh_f(gg[p]);
                    c[uc][j][p] = cn;
                    h_[p] = sig_f(go[p]) * tanh_f(cn);
                }
                if (t < DDEG - 1) {
                    uint32_t lo = bf16x2_pack(h_[1], h_[0]);
                    uint32_t hi = bf16x2_pack(h_[3], h_[2]);
                    int ks = uc * 2 + (j >> 1);
                    int slot = (j & 1) * 2;
                    *(ull*)(Awr + ks * 128 + lane * 4 + slot) = ((ull)hi << 32) | lo;
                } else {
                    if (node0 < NNODE)
                        *(float2*)(Hout + (size_t)node0 * 128 + u0) = make_float2(h_[0], h_[1]);
                    if (node1 < NNODE)
                        *(float2*)(Hout + (size_t)node1 * 128 + u0) = make_float2(h_[2], h_[3]);
                }
            }
        }
    }
}

// ---------------- final layer-2 combine: OUT=1 + sigmoid ----------------
__global__ void out_kernel(const float* __restrict__ h1, const float* __restrict__ H,
                           const float* __restrict__ Wself, const float* __restrict__ Wneigh,
                           const float* __restrict__ b, float* __restrict__ out, int Nrows)
{
    int gwarp = (blockIdx.x * blockDim.x + threadIdx.x) >> 5;
    int lane = threadIdx.x & 31;
    if (gwarp >= Nrows) return;
    float s = 0.f;
#pragma unroll
    for (int q = 0; q < 4; q++) {
        int k = lane + 32 * q;
        s += h1[(size_t)gwarp * 128 + k] * Wself[k] + H[(size_t)gwarp * 128 + k] * Wneigh[k];
    }
#pragma unroll
    for (int off = 16; off; off >>= 1) s += __shfl_xor_sync(0xFFFFFFFFu, s, off);
    if (lane == 0) out[gwarp] = sig_exact(s + b[0]);
}

// ---------------- launch ----------------
extern "C" void kernel_launch(void* const* d_in, const int* in_sizes, int n_in,
                              void* d_out, int out_size)
{
    const float* x       = (const float*)d_in[0];
    const int*   nbr     = (const int*)d_in[1];
    const float* Wih1    = (const float*)d_in[2];
    const float* Whh1    = (const float*)d_in[3];
    const float* bih1    = (const float*)d_in[4];
    const float* bhh1    = (const float*)d_in[5];
    const float* Wself1  = (const float*)d_in[6];
    const float* Wneigh1 = (const float*)d_in[7];
    const float* bneigh1 = (const float*)d_in[8];
    const float* Wih2    = (const float*)d_in[9];
    const float* Whh2    = (const float*)d_in[10];
    const float* bih2    = (const float*)d_in[11];
    const float* bhh2    = (const float*)d_in[12];
    const float* Wself2  = (const float*)d_in[13];
    const float* Wneigh2 = (const float*)d_in[14];
    const float* bneigh2 = (const float*)d_in[15];
    float* out = (float*)d_out;

    __half* Xp; float *H, *h1;
    cudaGetSymbolAddress((void**)&Xp, g_Xp);
    cudaGetSymbolAddress((void**)&H,  g_H);
    cudaGetSymbolAddress((void**)&h1, g_h1);

    cudaFuncSetAttribute(lstm_mma_kernel,     cudaFuncAttributeMaxDynamicSharedMemorySize, LSTM_SMEM);
    cudaFuncSetAttribute(hmma_proj_kernel,    cudaFuncAttributeMaxDynamicSharedMemorySize, PROJ_SMEM);
    cudaFuncSetAttribute(hmma_combine_kernel, cudaFuncAttributeMaxDynamicSharedMemorySize, CMB_SMEM);

    const int TB = 256;
    const int GRID = (NNODE + NODES_B - 1) / NODES_B;   // 139 <= 148: one wave

    // ---- layer 1 ----
    hmma_proj_kernel<<<GRID, NWARP * 32, PROJ_SMEM>>>(x, Wih1, bih1, bhh1, Xp);
    lstm_mma_kernel<<<GRID, NWARP * 32, LSTM_SMEM>>>(Xp, nbr, Whh1, H);
    hmma_combine_kernel<<<GRID, NWARP * 32, CMB_SMEM>>>(x, H, Wself1, Wneigh1, bneigh1, h1);

    // ---- layer 2 ----
    hmma_proj_kernel<<<GRID, NWARP * 32, PROJ_SMEM>>>(h1, Wih2, bih2, bhh2, Xp);
    lstm_mma_kernel<<<GRID, NWARP * 32, LSTM_SMEM>>>(Xp, nbr, Whh2, H);
    out_kernel<<<(NNODE * 32 + TB - 1) / TB, TB>>>(h1, H, Wself2, Wneigh2, bneigh2, out, NNODE);
}